// round 14
// baseline (speedup 1.0000x reference)
#include <cuda_runtime.h>
#include <cuda_bf16.h>
#include <cuda_fp16.h>
#include <cstdint>
#include <math.h>

#define N_NODES 50000
#define N_EDGES 800000
#define FEATS   128
#define MAXDEG  128                    // padded-CSR row stride (P(deg>127) ~ 0)

#define WS_SCALE 16777216.0f          // 2^24 fixed-point for wsum
#define PACK_MASK ((1ull << 40) - 1)

#define NQUADS (N_NODES * FEATS / 4)  // 1.6M float4 granules for fp16 convert

// ---------------- scratch (static __device__, no allocation) ----------------
__device__ unsigned long long g_pack[N_NODES];   // deg<<40 | fixedpoint wsum
__device__ unsigned long long g_epack[(size_t)N_NODES * MAXDEG]; // low32=src, high32=w bits
__device__ float g_aggF[(size_t)N_NODES * FEATS];
__device__ float g_ms[N_NODES];
__device__ __align__(16) __half g_featH[(size_t)N_NODES * FEATS];
__device__ __align__(16) unsigned int g_Wh[128 * 128];  // bf16x2 hi, concat-K layout
__device__ __align__(16) unsigned int g_Wl[128 * 128];  // bf16x2 lo

__device__ __forceinline__ float ex2f(float x) {
    float r;
    asm("ex2.approx.f32 %0, %1;" : "=f"(r) : "f"(x));
    return r;
}

// ---------------- K0: init pack + W split + feat->fp16 (one launch) --------
__global__ void k_prep(const float* __restrict__ W_pool,
                       const float* __restrict__ W_self,
                       const float* __restrict__ feat) {
    int i = blockIdx.x * blockDim.x + threadIdx.x;
    if (i < N_NODES) g_pack[i] = 0ull;
    if (i < 128 * 128) {
        int j = i >> 7;
        int w = i & 127;
        int k = 2 * w;
        const float* srcp = (k < FEATS) ? (W_self + (size_t)j * FEATS + k)
                                        : (W_pool + (size_t)j * FEATS + (k - FEATS));
        float x = srcp[0], y = srcp[1];
        float hx = __bfloat162float(__float2bfloat16(x));
        float hy = __bfloat162float(__float2bfloat16(y));
        __nv_bfloat16 a, b;
        a = __float2bfloat16(hx); b = __float2bfloat16(hy);
        g_Wh[i] = (uint32_t)__bfloat16_as_ushort(a) | ((uint32_t)__bfloat16_as_ushort(b) << 16);
        a = __float2bfloat16(x - hx); b = __float2bfloat16(y - hy);
        g_Wl[i] = (uint32_t)__bfloat16_as_ushort(a) | ((uint32_t)__bfloat16_as_ushort(b) << 16);
    }
    if (i < NQUADS) {
        float4 v = ((const float4*)feat)[i];
        __half2* o = (__half2*)g_featH;
        o[i * 2]     = __floats2half2_rn(v.x, v.y);
        o[i * 2 + 1] = __floats2half2_rn(v.z, v.w);
    }
}

// ---------------- K1: ONE edge pass — atomic gives rank, scatter raw w -----
__global__ void k_edges(const float* __restrict__ efeat, const int* __restrict__ src,
                        const int* __restrict__ dst) {
    int e = blockIdx.x * blockDim.x + threadIdx.x;
    if (e < N_EDGES) {
        int d = dst[e];
        float w = efeat[e];
        unsigned long long enc = (1ull << 40)
                               | (unsigned long long)__float2uint_rn(w * WS_SCALE);
        unsigned long long old = atomicAdd(&g_pack[d], enc);
        unsigned int r = (unsigned int)(old >> 40);
        g_epack[(size_t)d * MAXDEG + r] = (unsigned int)src[e]
                                        | ((unsigned long long)__float_as_uint(w) << 32);
    }
}

// ---------------- K2: warp-per-node gather over fp16 table; in-loop ex2 ----
__global__ void k_gather() {
    int node = (blockIdx.x * blockDim.x + threadIdx.x) >> 5;
    int lane = threadIdx.x & 31;
    if (node >= N_NODES) return;
    unsigned long long p = g_pack[node];
    int n = (int)(p >> 40);
    // coef = exp(-w/wsum) = ex2(w * nscale), nscale = -log2e * 2^24 / fixwsum
    float nscale = -1.442695040888963f * WS_SCALE / (float)(p & PACK_MASK);
    const uint4* row4 = (const uint4*)(g_epack + (size_t)node * MAXDEG);
    const char* fb = (const char*)g_featH + lane * 8;   // 4 halves per lane; row=256B
    float4 acc = make_float4(0.f, 0.f, 0.f, 0.f);
    float msum = 0.f;
    int nPairs = n >> 1;
    #pragma unroll 4
    for (int j = 0; j < nPairs; j++) {
        uint4 v = row4[j];                              // 2 packed edges, broadcast
        float c0 = ex2f(__uint_as_float(v.y) * nscale);
        float c1 = ex2f(__uint_as_float(v.w) * nscale);
        uint2 h0 = *(const uint2*)(fb + ((size_t)v.x << 8));
        uint2 h1 = *(const uint2*)(fb + ((size_t)v.z << 8));
        float2 a0 = __half22float2(*(__half2*)&h0.x);
        float2 b0 = __half22float2(*(__half2*)&h0.y);
        msum += c0;
        acc.x = fmaf(c0, a0.x, acc.x);
        acc.y = fmaf(c0, a0.y, acc.y);
        acc.z = fmaf(c0, b0.x, acc.z);
        acc.w = fmaf(c0, b0.y, acc.w);
        float2 a1 = __half22float2(*(__half2*)&h1.x);
        float2 b1 = __half22float2(*(__half2*)&h1.y);
        msum += c1;
        acc.x = fmaf(c1, a1.x, acc.x);
        acc.y = fmaf(c1, a1.y, acc.y);
        acc.z = fmaf(c1, b1.x, acc.z);
        acc.w = fmaf(c1, b1.y, acc.w);
    }
    if (n & 1) {
        unsigned long long v = ((const unsigned long long*)row4)[n - 1];
        unsigned int s = (unsigned int)v;
        float c = ex2f(__uint_as_float((unsigned int)(v >> 32)) * nscale);
        uint2 h = *(const uint2*)(fb + ((size_t)s << 8));
        float2 a = __half22float2(*(__half2*)&h.x);
        float2 b = __half22float2(*(__half2*)&h.y);
        msum += c;
        acc.x = fmaf(c, a.x, acc.x);
        acc.y = fmaf(c, a.y, acc.y);
        acc.z = fmaf(c, b.x, acc.z);
        acc.w = fmaf(c, b.y, acc.w);
    }
    float inv = 1.0f / fmaxf((float)n, 1.0f);
    ((float4*)g_aggF)[(size_t)node * 32 + lane] =
        make_float4(acc.x * inv, acc.y * inv, acc.z * inv, acc.w * inv);
    if (lane == 0) g_ms[node] = msum * inv;
}

// ============================================================================
// K3: split-bf16 GEMM on mma.sync (HMMA). B pre-split (g_Wh/g_Wl).
// ============================================================================

#define MMA_BF16(d, A0, A1, A2, A3, B0, B1)                                  \
    asm volatile(                                                            \
        "mma.sync.aligned.m16n8k16.row.col.f32.bf16.bf16.f32 "               \
        "{%0,%1,%2,%3}, {%4,%5,%6,%7}, {%8,%9}, {%0,%1,%2,%3};"              \
        : "+f"(d[0]), "+f"(d[1]), "+f"(d[2]), "+f"(d[3])                     \
        : "r"(A0), "r"(A1), "r"(A2), "r"(A3), "r"(B0), "r"(B1))

__device__ __forceinline__ uint32_t pack_bf16(float a, float b) {
    __nv_bfloat16 x = __float2bfloat16(a);
    __nv_bfloat16 y = __float2bfloat16(b);
    return (uint32_t)__bfloat16_as_ushort(x) | ((uint32_t)__bfloat16_as_ushort(y) << 16);
}

// smem: 4 tiles of 128 rows x (16 data + 2 pad) words = 9216 B each
#define T_AH 0
#define T_AL 9216
#define T_BH 18432
#define T_BL 27648
#define ROWB 72
#define ROWW 18

__global__ __launch_bounds__(256, 2) void k_gemm(
        const float* __restrict__ feat,
        const float* __restrict__ b_pool,
        const float* __restrict__ b_self,
        float* __restrict__ out) {
    __shared__ __align__(16) char sm[36864];

    int tid  = threadIdx.x;
    int wid  = tid >> 5;
    int lane = tid & 31;
    int wr = wid >> 1;
    int wc = wid & 1;
    int lr = lane >> 2;
    int lc = lane & 3;
    int blockRow = blockIdx.x * 128;

    float acc[2][8][4];
    #pragma unroll
    for (int mt = 0; mt < 2; mt++)
        #pragma unroll
        for (int nt = 0; nt < 8; nt++)
            #pragma unroll
            for (int i = 0; i < 4; i++) acc[mt][nt][i] = 0.f;

    for (int c = 0; c < 8; c++) {
        const float* Asrc = (c < 4) ? feat : g_aggF;
        int kOff = (c & 3) * 32;

        __syncthreads();
        // ---- A: 1024 float4 slots, split to bf16 hi/lo ----
        #pragma unroll
        for (int it = 0; it < 4; it++) {
            int idx = tid + it * 256;
            int row = idx >> 3;
            int q   = idx & 7;
            int k0  = q * 4;
            int rg  = blockRow + row;
            int rgc = (rg < N_NODES) ? rg : (N_NODES - 1);
            float4 v = *(const float4*)(Asrc + (size_t)rgc * FEATS + kOff + k0);
            float hx = __bfloat162float(__float2bfloat16(v.x));
            float hy = __bfloat162float(__float2bfloat16(v.y));
            float hz = __bfloat162float(__float2bfloat16(v.z));
            float hw = __bfloat162float(__float2bfloat16(v.w));
            uint2 hp, lp;
            hp.x = pack_bf16(hx, hy);             hp.y = pack_bf16(hz, hw);
            lp.x = pack_bf16(v.x - hx, v.y - hy); lp.y = pack_bf16(v.z - hz, v.w - hw);
            *(uint2*)(sm + T_AH + row * ROWB + q * 8) = hp;
            *(uint2*)(sm + T_AL + row * ROWB + q * 8) = lp;
        }
        // ---- B: copy pre-split weights; 16B gmem loads, 2x 8B smem stores ----
        #pragma unroll
        for (int it = 0; it < 4; it++) {
            int idx = tid + it * 256;
            int row = idx >> 3;
            int t8  = idx & 7;
            int hl  = t8 >> 2;
            int q   = t8 & 3;
            const unsigned int* srcw = (hl ? g_Wl : g_Wh) + row * 128 + c * 16 + q * 4;
            uint4 v = *(const uint4*)srcw;
            char* dstp = sm + (hl ? T_BL : T_BH) + row * ROWB + q * 16;
            *(uint2*)(dstp)     = make_uint2(v.x, v.y);
            *(uint2*)(dstp + 8) = make_uint2(v.z, v.w);
        }
        __syncthreads();

        const uint32_t* pAH = (const uint32_t*)(sm + T_AH);
        const uint32_t* pAL = (const uint32_t*)(sm + T_AL);
        const uint32_t* pBH = (const uint32_t*)(sm + T_BH);
        const uint32_t* pBL = (const uint32_t*)(sm + T_BL);

        #pragma unroll
        for (int ks = 0; ks < 2; ks++) {
            int kb2 = ks * 8;
            uint32_t ah[2][4], al[2][4];
            #pragma unroll
            for (int mt = 0; mt < 2; mt++) {
                int r0 = wr * 32 + mt * 16 + lr;
                int i00 = r0 * ROWW + kb2 + lc;
                ah[mt][0] = pAH[i00];
                ah[mt][1] = pAH[i00 + 8 * ROWW];
                ah[mt][2] = pAH[i00 + 4];
                ah[mt][3] = pAH[i00 + 8 * ROWW + 4];
                al[mt][0] = pAL[i00];
                al[mt][1] = pAL[i00 + 8 * ROWW];
                al[mt][2] = pAL[i00 + 4];
                al[mt][3] = pAL[i00 + 8 * ROWW + 4];
            }
            #pragma unroll
            for (int nt = 0; nt < 8; nt++) {
                int n0 = wc * 64 + nt * 8 + lr;
                int j0 = n0 * ROWW + kb2 + lc;
                uint32_t bh0 = pBH[j0], bh1 = pBH[j0 + 4];
                uint32_t bl0 = pBL[j0], bl1 = pBL[j0 + 4];
                #pragma unroll
                for (int mt = 0; mt < 2; mt++) {
                    MMA_BF16(acc[mt][nt], ah[mt][0], ah[mt][1], ah[mt][2], ah[mt][3], bh0, bh1);
                    MMA_BF16(acc[mt][nt], ah[mt][0], ah[mt][1], ah[mt][2], ah[mt][3], bl0, bl1);
                    MMA_BF16(acc[mt][nt], al[mt][0], al[mt][1], al[mt][2], al[mt][3], bh0, bh1);
                }
            }
        }
    }

    // ---- epilogue: + b_self + ms * b_pool ----
    #pragma unroll
    for (int mt = 0; mt < 2; mt++) {
        int r0 = blockRow + wr * 32 + mt * 16 + lr;
        int r1 = r0 + 8;
        float ms0 = (r0 < N_NODES) ? g_ms[r0] : 0.f;
        float ms1 = (r1 < N_NODES) ? g_ms[r1] : 0.f;
        #pragma unroll
        for (int nt = 0; nt < 8; nt++) {
            int C = wc * 64 + nt * 8 + lc * 2;
            float2 bs = *(const float2*)(b_self + C);
            float2 bp = *(const float2*)(b_pool + C);
            if (r0 < N_NODES) {
                float2 o;
                o.x = acc[mt][nt][0] + bs.x + ms0 * bp.x;
                o.y = acc[mt][nt][1] + bs.y + ms0 * bp.y;
                *(float2*)(out + (size_t)r0 * FEATS + C) = o;
            }
            if (r1 < N_NODES) {
                float2 o;
                o.x = acc[mt][nt][2] + bs.x + ms1 * bp.x;
                o.y = acc[mt][nt][3] + bs.y + ms1 * bp.y;
                *(float2*)(out + (size_t)r1 * FEATS + C) = o;
            }
        }
    }
}

// ---------------- launch ----------------
extern "C" void kernel_launch(void* const* d_in, const int* in_sizes, int n_in,
                              void* d_out, int out_size) {
    const float* feat   = (const float*)d_in[0];
    const float* efeat  = (const float*)d_in[1];
    const int*   src    = (const int*)d_in[2];
    const int*   dst    = (const int*)d_in[3];
    const float* W_pool = (const float*)d_in[4];
    const float* b_pool = (const float*)d_in[5];
    const float* W_self = (const float*)d_in[6];
    const float* b_self = (const float*)d_in[7];
    float* out = (float*)d_out;

    k_prep<<<(NQUADS + 255) / 256, 256>>>(W_pool, W_self, feat);
    k_edges<<<(N_EDGES + 255) / 256, 256>>>(efeat, src, dst);
    k_gather<<<(N_NODES * 32 + 255) / 256, 256>>>();
    k_gemm<<<(N_NODES + 127) / 128, 256>>>(feat, b_pool, b_self, out);
}

// round 15
// speedup vs baseline: 1.2626x; 1.2626x over previous
#include <cuda_runtime.h>
#include <cuda_bf16.h>
#include <cstdint>
#include <math.h>

#define N_NODES 50000
#define N_EDGES 800000
#define FEATS   128
#define MAXDEG  128                    // padded-CSR row stride (P(deg>127) ~ 0)

#define WS_SCALE 16777216.0f          // 2^24 fixed-point for wsum
#define PACK_MASK ((1ull << 40) - 1)

// ---------------- scratch (static __device__, no allocation) ----------------
__device__ unsigned long long g_pack[N_NODES];   // deg<<40 | fixedpoint wsum
__device__ int   g_rank[N_EDGES];                // rank of edge within dst bucket
__device__ unsigned long long g_epack[(size_t)N_NODES * MAXDEG]; // low32=src, high32=m bits
__device__ float g_aggF[(size_t)N_NODES * FEATS];
__device__ float g_ms[N_NODES];
__device__ __align__(16) unsigned int g_Wh[128 * 128];  // bf16x2 hi, concat-K layout
__device__ __align__(16) unsigned int g_Wl[128 * 128];  // bf16x2 lo

// ---------------- K0: fused init (zero pack) + W split ----------------
__global__ void k_prep(const float* __restrict__ W_pool,
                       const float* __restrict__ W_self) {
    int i = blockIdx.x * blockDim.x + threadIdx.x;
    if (i < N_NODES) g_pack[i] = 0ull;
    if (i < 128 * 128) {
        int j = i >> 7;
        int w = i & 127;
        int k = 2 * w;
        const float* srcp = (k < FEATS) ? (W_self + (size_t)j * FEATS + k)
                                        : (W_pool + (size_t)j * FEATS + (k - FEATS));
        float x = srcp[0], y = srcp[1];
        float hx = __bfloat162float(__float2bfloat16(x));
        float hy = __bfloat162float(__float2bfloat16(y));
        __nv_bfloat16 a, b;
        a = __float2bfloat16(hx); b = __float2bfloat16(hy);
        g_Wh[i] = (uint32_t)__bfloat16_as_ushort(a) | ((uint32_t)__bfloat16_as_ushort(b) << 16);
        a = __float2bfloat16(x - hx); b = __float2bfloat16(y - hy);
        g_Wl[i] = (uint32_t)__bfloat16_as_ushort(a) | ((uint32_t)__bfloat16_as_ushort(b) << 16);
    }
}

// ---------------- K1: fused deg+wsum atomic, rank capture ----------------
__global__ void k_stats(const float* __restrict__ efeat, const int* __restrict__ dst) {
    int e = blockIdx.x * blockDim.x + threadIdx.x;
    if (e < N_EDGES) {
        int d = dst[e];
        unsigned long long enc = (1ull << 40)
                               | (unsigned long long)__float2uint_rn(efeat[e] * WS_SCALE);
        unsigned long long old = atomicAdd(&g_pack[d], enc);
        g_rank[e] = (int)(old >> 40);
    }
}

// ---------------- K2: fill padded CSR with precomputed coefficient ----------
__global__ void k_fill(const float* __restrict__ efeat, const int* __restrict__ src,
                       const int* __restrict__ dst) {
    int e = blockIdx.x * blockDim.x + threadIdx.x;
    if (e < N_EDGES) {
        int d = dst[e];
        unsigned long long p = g_pack[d];
        float m = __expf(-__fdividef(efeat[e] * WS_SCALE, (float)(p & PACK_MASK)));
        size_t slot = (size_t)d * MAXDEG + (unsigned int)g_rank[e];
        g_epack[slot] = (unsigned int)src[e]
                      | ((unsigned long long)__float_as_uint(m) << 32);
    }
}

// ---------------- K3: warp-per-node gather, 2 edges per LDG.128 ------------
__global__ void k_gather(const float* __restrict__ feat) {
    int node = (blockIdx.x * blockDim.x + threadIdx.x) >> 5;
    int lane = threadIdx.x & 31;
    if (node >= N_NODES) return;
    int n = (int)(g_pack[node] >> 40);
    const uint4* row4 = (const uint4*)(g_epack + (size_t)node * MAXDEG);
    const char* fb = (const char*)feat + lane * 16;   // per-lane feature base
    float4 acc = make_float4(0.f, 0.f, 0.f, 0.f);
    float msum = 0.f;
    int nPairs = n >> 1;
    #pragma unroll 4
    for (int j = 0; j < nPairs; j++) {
        uint4 v = row4[j];                            // 2 packed edges, broadcast
        float c0 = __uint_as_float(v.y);
        float c1 = __uint_as_float(v.w);
        float4 f0 = *(const float4*)(fb + ((size_t)v.x << 9));
        float4 f1 = *(const float4*)(fb + ((size_t)v.z << 9));
        msum += c0;
        acc.x = fmaf(c0, f0.x, acc.x);
        acc.y = fmaf(c0, f0.y, acc.y);
        acc.z = fmaf(c0, f0.z, acc.z);
        acc.w = fmaf(c0, f0.w, acc.w);
        msum += c1;
        acc.x = fmaf(c1, f1.x, acc.x);
        acc.y = fmaf(c1, f1.y, acc.y);
        acc.z = fmaf(c1, f1.z, acc.z);
        acc.w = fmaf(c1, f1.w, acc.w);
    }
    if (n & 1) {
        unsigned long long v = ((const unsigned long long*)row4)[n - 1];
        unsigned int s = (unsigned int)v;
        float c = __uint_as_float((unsigned int)(v >> 32));
        float4 f = *(const float4*)(fb + ((size_t)s << 9));
        msum += c;
        acc.x = fmaf(c, f.x, acc.x);
        acc.y = fmaf(c, f.y, acc.y);
        acc.z = fmaf(c, f.z, acc.z);
        acc.w = fmaf(c, f.w, acc.w);
    }
    float inv = 1.0f / fmaxf((float)n, 1.0f);
    ((float4*)g_aggF)[(size_t)node * 32 + lane] =
        make_float4(acc.x * inv, acc.y * inv, acc.z * inv, acc.w * inv);
    if (lane == 0) g_ms[node] = msum * inv;
}

// ============================================================================
// K4: split-bf16 GEMM on mma.sync (HMMA), ldmatrix fragment loads.
// Row stride 80B: 8-row ldmatrix groups hit all 32 banks once (conflict-free).
// ============================================================================

#define MMA_BF16(d, A0, A1, A2, A3, B0, B1)                                  \
    asm volatile(                                                            \
        "mma.sync.aligned.m16n8k16.row.col.f32.bf16.bf16.f32 "               \
        "{%0,%1,%2,%3}, {%4,%5,%6,%7}, {%8,%9}, {%0,%1,%2,%3};"              \
        : "+f"(d[0]), "+f"(d[1]), "+f"(d[2]), "+f"(d[3])                     \
        : "r"(A0), "r"(A1), "r"(A2), "r"(A3), "r"(B0), "r"(B1))

#define LDSM_X4(r, a)                                                        \
    asm volatile("ldmatrix.sync.aligned.m8n8.x4.shared.b16 {%0,%1,%2,%3}, [%4];" \
        : "=r"((r)[0]), "=r"((r)[1]), "=r"((r)[2]), "=r"((r)[3]) : "r"(a))

#define LDSM_X2(r, a)                                                        \
    asm volatile("ldmatrix.sync.aligned.m8n8.x2.shared.b16 {%0,%1}, [%2];"   \
        : "=r"((r)[0]), "=r"((r)[1]) : "r"(a))

__device__ __forceinline__ uint32_t pack_bf16(float a, float b) {
    __nv_bfloat16 x = __float2bfloat16(a);
    __nv_bfloat16 y = __float2bfloat16(b);
    return (uint32_t)__bfloat16_as_ushort(x) | ((uint32_t)__bfloat16_as_ushort(y) << 16);
}

__device__ __forceinline__ uint32_t smem_u32(const void* p) {
    uint32_t a;
    asm("{ .reg .u64 t; cvta.to.shared.u64 t, %1; cvt.u32.u64 %0, t; }" : "=r"(a) : "l"(p));
    return a;
}

// smem: 4 tiles of 128 rows x 80 bytes = 10240 B each
#define ROWB 80
#define T_AH 0
#define T_AL 10240
#define T_BH 20480
#define T_BL 30720

__global__ __launch_bounds__(256, 2) void k_gemm(
        const float* __restrict__ feat,
        const float* __restrict__ b_pool,
        const float* __restrict__ b_self,
        float* __restrict__ out) {
    __shared__ __align__(16) char sm[40960];

    int tid  = threadIdx.x;
    int wid  = tid >> 5;
    int lane = tid & 31;
    int wr = wid >> 1;
    int wc = wid & 1;
    int lr = lane >> 2;
    int lc = lane & 3;
    int blockRow = blockIdx.x * 128;

    // ldmatrix per-thread base addresses (chunk-invariant)
    uint32_t smb = smem_u32(sm);
    uint32_t aBase = smb + T_AH + (uint32_t)((wr * 32 + (lane & 15)) * ROWB
                                             + (lane >> 4) * 16);
    uint32_t bBase = smb + T_BH + (uint32_t)((wc * 64 + (lane & 7)) * ROWB
                                             + ((lane >> 3) & 1) * 16);

    float acc[2][8][4];
    #pragma unroll
    for (int mt = 0; mt < 2; mt++)
        #pragma unroll
        for (int nt = 0; nt < 8; nt++)
            #pragma unroll
            for (int i = 0; i < 4; i++) acc[mt][nt][i] = 0.f;

    for (int c = 0; c < 8; c++) {
        const float* Asrc = (c < 4) ? feat : g_aggF;
        int kOff = (c & 3) * 32;

        __syncthreads();
        // ---- A: 1024 float4 slots, split to bf16 hi/lo ----
        #pragma unroll
        for (int it = 0; it < 4; it++) {
            int idx = tid + it * 256;
            int row = idx >> 3;
            int q   = idx & 7;
            int k0  = q * 4;
            int rg  = blockRow + row;
            int rgc = (rg < N_NODES) ? rg : (N_NODES - 1);
            float4 v = *(const float4*)(Asrc + (size_t)rgc * FEATS + kOff + k0);
            float hx = __bfloat162float(__float2bfloat16(v.x));
            float hy = __bfloat162float(__float2bfloat16(v.y));
            float hz = __bfloat162float(__float2bfloat16(v.z));
            float hw = __bfloat162float(__float2bfloat16(v.w));
            uint2 hp, lp;
            hp.x = pack_bf16(hx, hy);             hp.y = pack_bf16(hz, hw);
            lp.x = pack_bf16(v.x - hx, v.y - hy); lp.y = pack_bf16(v.z - hz, v.w - hw);
            *(uint2*)(sm + T_AH + row * ROWB + q * 8) = hp;
            *(uint2*)(sm + T_AL + row * ROWB + q * 8) = lp;
        }
        // ---- B: copy pre-split weights; 16B gmem loads, 2x 8B smem stores ----
        #pragma unroll
        for (int it = 0; it < 4; it++) {
            int idx = tid + it * 256;
            int row = idx >> 3;
            int t8  = idx & 7;
            int hl  = t8 >> 2;
            int q   = t8 & 3;
            const unsigned int* srcw = (hl ? g_Wl : g_Wh) + row * 128 + c * 16 + q * 4;
            uint4 v = *(const uint4*)srcw;
            char* dstp = sm + (hl ? T_BL : T_BH) + row * ROWB + q * 16;
            *(uint2*)(dstp)     = make_uint2(v.x, v.y);
            *(uint2*)(dstp + 8) = make_uint2(v.z, v.w);
        }
        __syncthreads();

        #pragma unroll
        for (int ks = 0; ks < 2; ks++) {
            uint32_t ah[2][4], al[2][4];
            #pragma unroll
            for (int mt = 0; mt < 2; mt++) {
                LDSM_X4(ah[mt], aBase + mt * (16 * ROWB) + ks * 32);
                LDSM_X4(al[mt], aBase + (T_AL - T_AH) + mt * (16 * ROWB) + ks * 32);
            }
            #pragma unroll
            for (int nt = 0; nt < 8; nt++) {
                uint32_t bh[2], bl[2];
                LDSM_X2(bh, bBase + nt * (8 * ROWB) + ks * 32);
                LDSM_X2(bl, bBase + (T_BL - T_BH) + nt * (8 * ROWB) + ks * 32);
                #pragma unroll
                for (int mt = 0; mt < 2; mt++) {
                    MMA_BF16(acc[mt][nt], ah[mt][0], ah[mt][1], ah[mt][2], ah[mt][3], bh[0], bh[1]);
                    MMA_BF16(acc[mt][nt], ah[mt][0], ah[mt][1], ah[mt][2], ah[mt][3], bl[0], bl[1]);
                    MMA_BF16(acc[mt][nt], al[mt][0], al[mt][1], al[mt][2], al[mt][3], bh[0], bh[1]);
                }
            }
        }
    }

    // ---- epilogue: + b_self + ms * b_pool ----
    #pragma unroll
    for (int mt = 0; mt < 2; mt++) {
        int r0 = blockRow + wr * 32 + mt * 16 + lr;
        int r1 = r0 + 8;
        float ms0 = (r0 < N_NODES) ? g_ms[r0] : 0.f;
        float ms1 = (r1 < N_NODES) ? g_ms[r1] : 0.f;
        #pragma unroll
        for (int nt = 0; nt < 8; nt++) {
            int C = wc * 64 + nt * 8 + lc * 2;
            float2 bs = *(const float2*)(b_self + C);
            float2 bp = *(const float2*)(b_pool + C);
            if (r0 < N_NODES) {
                float2 o;
                o.x = acc[mt][nt][0] + bs.x + ms0 * bp.x;
                o.y = acc[mt][nt][1] + bs.y + ms0 * bp.y;
                *(float2*)(out + (size_t)r0 * FEATS + C) = o;
            }
            if (r1 < N_NODES) {
                float2 o;
                o.x = acc[mt][nt][2] + bs.x + ms1 * bp.x;
                o.y = acc[mt][nt][3] + bs.y + ms1 * bp.y;
                *(float2*)(out + (size_t)r1 * FEATS + C) = o;
            }
        }
    }
}

// ---------------- launch ----------------
extern "C" void kernel_launch(void* const* d_in, const int* in_sizes, int n_in,
                              void* d_out, int out_size) {
    const float* feat   = (const float*)d_in[0];
    const float* efeat  = (const float*)d_in[1];
    const int*   src    = (const int*)d_in[2];
    const int*   dst    = (const int*)d_in[3];
    const float* W_pool = (const float*)d_in[4];
    const float* b_pool = (const float*)d_in[5];
    const float* W_self = (const float*)d_in[6];
    const float* b_self = (const float*)d_in[7];
    float* out = (float*)d_out;

    k_prep<<<(N_NODES + 255) / 256, 256>>>(W_pool, W_self);
    k_stats<<<(N_EDGES + 255) / 256, 256>>>(efeat, dst);
    k_fill<<<(N_EDGES + 255) / 256, 256>>>(efeat, src, dst);
    k_gather<<<(N_NODES * 32 + 255) / 256, 256>>>(feat);
    k_gemm<<<(N_NODES + 127) / 128, 256>>>(feat, b_pool, b_self, out);
}

// round 16
// speedup vs baseline: 1.2871x; 1.0194x over previous
#include <cuda_runtime.h>
#include <cuda_bf16.h>
#include <cstdint>
#include <math.h>

#define N_NODES 50000
#define N_EDGES 800000
#define FEATS   128
#define MAXDEG  128                    // padded-CSR row stride (P(deg>127) ~ 0)

#define WS_SCALE 16777216.0f          // 2^24 fixed-point for wsum
#define PACK_MASK ((1ull << 40) - 1)

// ---------------- scratch (static __device__, no allocation) ----------------
__device__ unsigned long long g_pack[N_NODES];   // deg<<40 | fixedpoint wsum
__device__ int   g_rank[N_EDGES];                // rank of edge within dst bucket
__device__ unsigned long long g_epack[(size_t)N_NODES * MAXDEG]; // low32=src, high32=m bits
__device__ float g_aggF[(size_t)N_NODES * FEATS];
__device__ float g_ms[N_NODES];
__device__ __align__(16) unsigned int g_Wh[128 * 128];  // bf16x2 hi, concat-K layout
__device__ __align__(16) unsigned int g_Wl[128 * 128];  // bf16x2 lo

// ---------------- K0: fused init (zero pack) + W split ----------------
__global__ void k_prep(const float* __restrict__ W_pool,
                       const float* __restrict__ W_self) {
    int i = blockIdx.x * blockDim.x + threadIdx.x;
    if (i < N_NODES) g_pack[i] = 0ull;
    if (i < 128 * 128) {
        int j = i >> 7;
        int w = i & 127;
        int k = 2 * w;
        const float* srcp = (k < FEATS) ? (W_self + (size_t)j * FEATS + k)
                                        : (W_pool + (size_t)j * FEATS + (k - FEATS));
        float x = srcp[0], y = srcp[1];
        float hx = __bfloat162float(__float2bfloat16(x));
        float hy = __bfloat162float(__float2bfloat16(y));
        __nv_bfloat16 a, b;
        a = __float2bfloat16(hx); b = __float2bfloat16(hy);
        g_Wh[i] = (uint32_t)__bfloat16_as_ushort(a) | ((uint32_t)__bfloat16_as_ushort(b) << 16);
        a = __float2bfloat16(x - hx); b = __float2bfloat16(y - hy);
        g_Wl[i] = (uint32_t)__bfloat16_as_ushort(a) | ((uint32_t)__bfloat16_as_ushort(b) << 16);
    }
}

// ---------------- K1: fused deg+wsum atomic, rank capture ----------------
__global__ void k_stats(const float* __restrict__ efeat, const int* __restrict__ dst) {
    int e = blockIdx.x * blockDim.x + threadIdx.x;
    if (e < N_EDGES) {
        int d = dst[e];
        unsigned long long enc = (1ull << 40)
                               | (unsigned long long)__float2uint_rn(efeat[e] * WS_SCALE);
        unsigned long long old = atomicAdd(&g_pack[d], enc);
        g_rank[e] = (int)(old >> 40);
    }
}

// ---------------- K2: fill padded CSR with precomputed coefficient ----------
__global__ void k_fill(const float* __restrict__ efeat, const int* __restrict__ src,
                       const int* __restrict__ dst) {
    int e = blockIdx.x * blockDim.x + threadIdx.x;
    if (e < N_EDGES) {
        int d = dst[e];
        unsigned long long p = g_pack[d];
        float m = __expf(-__fdividef(efeat[e] * WS_SCALE, (float)(p & PACK_MASK)));
        size_t slot = (size_t)d * MAXDEG + (unsigned int)g_rank[e];
        g_epack[slot] = (unsigned int)src[e]
                      | ((unsigned long long)__float_as_uint(m) << 32);
    }
}

// ---------------- K3: warp-per-node gather, 2 edges per LDG.128 ------------
__global__ void k_gather(const float* __restrict__ feat) {
    int node = (blockIdx.x * blockDim.x + threadIdx.x) >> 5;
    int lane = threadIdx.x & 31;
    if (node >= N_NODES) return;
    int n = (int)(g_pack[node] >> 40);
    const uint4* row4 = (const uint4*)(g_epack + (size_t)node * MAXDEG);
    const char* fb = (const char*)feat + lane * 16;   // per-lane feature base
    float4 acc = make_float4(0.f, 0.f, 0.f, 0.f);
    float msum = 0.f;
    int nPairs = n >> 1;
    #pragma unroll 4
    for (int j = 0; j < nPairs; j++) {
        uint4 v = row4[j];                            // 2 packed edges, broadcast
        float c0 = __uint_as_float(v.y);
        float c1 = __uint_as_float(v.w);
        float4 f0 = *(const float4*)(fb + ((size_t)v.x << 9));
        float4 f1 = *(const float4*)(fb + ((size_t)v.z << 9));
        msum += c0;
        acc.x = fmaf(c0, f0.x, acc.x);
        acc.y = fmaf(c0, f0.y, acc.y);
        acc.z = fmaf(c0, f0.z, acc.z);
        acc.w = fmaf(c0, f0.w, acc.w);
        msum += c1;
        acc.x = fmaf(c1, f1.x, acc.x);
        acc.y = fmaf(c1, f1.y, acc.y);
        acc.z = fmaf(c1, f1.z, acc.z);
        acc.w = fmaf(c1, f1.w, acc.w);
    }
    if (n & 1) {
        unsigned long long v = ((const unsigned long long*)row4)[n - 1];
        unsigned int s = (unsigned int)v;
        float c = __uint_as_float((unsigned int)(v >> 32));
        float4 f = *(const float4*)(fb + ((size_t)s << 9));
        msum += c;
        acc.x = fmaf(c, f.x, acc.x);
        acc.y = fmaf(c, f.y, acc.y);
        acc.z = fmaf(c, f.z, acc.z);
        acc.w = fmaf(c, f.w, acc.w);
    }
    float inv = 1.0f / fmaxf((float)n, 1.0f);
    ((float4*)g_aggF)[(size_t)node * 32 + lane] =
        make_float4(acc.x * inv, acc.y * inv, acc.z * inv, acc.w * inv);
    if (lane == 0) g_ms[node] = msum * inv;
}

// ============================================================================
// Split GEMMs (R12-validated mainloop, K=128 each):
//   k_gemm_self: out  = feat @ W_self^T + b_self          (overlaps edge pipe)
//   k_gemm_pool: out += aggF @ W_pool^T + ms * b_pool
// ============================================================================

#define MMA_BF16(d, A0, A1, A2, A3, B0, B1)                                  \
    asm volatile(                                                            \
        "mma.sync.aligned.m16n8k16.row.col.f32.bf16.bf16.f32 "               \
        "{%0,%1,%2,%3}, {%4,%5,%6,%7}, {%8,%9}, {%0,%1,%2,%3};"              \
        : "+f"(d[0]), "+f"(d[1]), "+f"(d[2]), "+f"(d[3])                     \
        : "r"(A0), "r"(A1), "r"(A2), "r"(A3), "r"(B0), "r"(B1))

__device__ __forceinline__ uint32_t pack_bf16(float a, float b) {
    __nv_bfloat16 x = __float2bfloat16(a);
    __nv_bfloat16 y = __float2bfloat16(b);
    return (uint32_t)__bfloat16_as_ushort(x) | ((uint32_t)__bfloat16_as_ushort(y) << 16);
}

// smem: 4 tiles of 128 rows x (16 data + 2 pad) words = 9216 B each
#define T_AH 0
#define T_AL 9216
#define T_BH 18432
#define T_BL 27648
#define ROWB 72
#define ROWW 18

// POOL=0: A=feat, B words 0..63, out = acc + bs
// POOL=1: A=g_aggF, B words 64..127, out += acc + ms*bp
template<int POOL>
__device__ __forceinline__ void gemm_body(const float* __restrict__ Asrc,
                                          const float* __restrict__ bias,
                                          float* __restrict__ out) {
    __shared__ __align__(16) char sm[36864];

    int tid  = threadIdx.x;
    int wid  = tid >> 5;
    int lane = tid & 31;
    int wr = wid >> 1;
    int wc = wid & 1;
    int lr = lane >> 2;
    int lc = lane & 3;
    int blockRow = blockIdx.x * 128;

    float acc[2][8][4];
    #pragma unroll
    for (int mt = 0; mt < 2; mt++)
        #pragma unroll
        for (int nt = 0; nt < 8; nt++)
            #pragma unroll
            for (int i = 0; i < 4; i++) acc[mt][nt][i] = 0.f;

    for (int c = 0; c < 4; c++) {
        int kOff = c * 32;
        __syncthreads();
        // ---- A: 1024 float4 slots, split to bf16 hi/lo ----
        #pragma unroll
        for (int it = 0; it < 4; it++) {
            int idx = tid + it * 256;
            int row = idx >> 3;
            int q   = idx & 7;
            int k0  = q * 4;
            int rg  = blockRow + row;
            int rgc = (rg < N_NODES) ? rg : (N_NODES - 1);
            float4 v = *(const float4*)(Asrc + (size_t)rgc * FEATS + kOff + k0);
            float hx = __bfloat162float(__float2bfloat16(v.x));
            float hy = __bfloat162float(__float2bfloat16(v.y));
            float hz = __bfloat162float(__float2bfloat16(v.z));
            float hw = __bfloat162float(__float2bfloat16(v.w));
            uint2 hp, lp;
            hp.x = pack_bf16(hx, hy);             hp.y = pack_bf16(hz, hw);
            lp.x = pack_bf16(v.x - hx, v.y - hy); lp.y = pack_bf16(v.z - hz, v.w - hw);
            *(uint2*)(sm + T_AH + row * ROWB + q * 8) = hp;
            *(uint2*)(sm + T_AL + row * ROWB + q * 8) = lp;
        }
        // ---- B: copy pre-split weights ----
        #pragma unroll
        for (int it = 0; it < 4; it++) {
            int idx = tid + it * 256;
            int row = idx >> 3;
            int t8  = idx & 7;
            int hl  = t8 >> 2;
            int q   = t8 & 3;
            const unsigned int* srcw = (hl ? g_Wl : g_Wh) + row * 128
                                     + POOL * 64 + c * 16 + q * 4;
            uint4 v = *(const uint4*)srcw;
            char* dstp = sm + (hl ? T_BL : T_BH) + row * ROWB + q * 16;
            *(uint2*)(dstp)     = make_uint2(v.x, v.y);
            *(uint2*)(dstp + 8) = make_uint2(v.z, v.w);
        }
        __syncthreads();

        const uint32_t* pAH = (const uint32_t*)(sm + T_AH);
        const uint32_t* pAL = (const uint32_t*)(sm + T_AL);
        const uint32_t* pBH = (const uint32_t*)(sm + T_BH);
        const uint32_t* pBL = (const uint32_t*)(sm + T_BL);

        #pragma unroll
        for (int ks = 0; ks < 2; ks++) {
            int kb2 = ks * 8;
            uint32_t ah[2][4], al[2][4];
            #pragma unroll
            for (int mt = 0; mt < 2; mt++) {
                int r0 = wr * 32 + mt * 16 + lr;
                int i00 = r0 * ROWW + kb2 + lc;
                ah[mt][0] = pAH[i00];
                ah[mt][1] = pAH[i00 + 8 * ROWW];
                ah[mt][2] = pAH[i00 + 4];
                ah[mt][3] = pAH[i00 + 8 * ROWW + 4];
                al[mt][0] = pAL[i00];
                al[mt][1] = pAL[i00 + 8 * ROWW];
                al[mt][2] = pAL[i00 + 4];
                al[mt][3] = pAL[i00 + 8 * ROWW + 4];
            }
            #pragma unroll
            for (int nt = 0; nt < 8; nt++) {
                int n0 = wc * 64 + nt * 8 + lr;
                int j0 = n0 * ROWW + kb2 + lc;
                uint32_t bh0 = pBH[j0], bh1 = pBH[j0 + 4];
                uint32_t bl0 = pBL[j0], bl1 = pBL[j0 + 4];
                #pragma unroll
                for (int mt = 0; mt < 2; mt++) {
                    MMA_BF16(acc[mt][nt], ah[mt][0], ah[mt][1], ah[mt][2], ah[mt][3], bh0, bh1);
                    MMA_BF16(acc[mt][nt], ah[mt][0], ah[mt][1], ah[mt][2], ah[mt][3], bl0, bl1);
                    MMA_BF16(acc[mt][nt], al[mt][0], al[mt][1], al[mt][2], al[mt][3], bh0, bh1);
                }
            }
        }
    }

    // ---- epilogue ----
    #pragma unroll
    for (int mt = 0; mt < 2; mt++) {
        int r0 = blockRow + wr * 32 + mt * 16 + lr;
        int r1 = r0 + 8;
        float ms0 = 0.f, ms1 = 0.f;
        if (POOL) {
            ms0 = (r0 < N_NODES) ? g_ms[r0] : 0.f;
            ms1 = (r1 < N_NODES) ? g_ms[r1] : 0.f;
        }
        #pragma unroll
        for (int nt = 0; nt < 8; nt++) {
            int C = wc * 64 + nt * 8 + lc * 2;
            float2 bv = *(const float2*)(bias + C);
            if (r0 < N_NODES) {
                float* op = out + (size_t)r0 * FEATS + C;
                float2 o;
                if (POOL) {
                    float2 cur = *(float2*)op;
                    o.x = cur.x + acc[mt][nt][0] + ms0 * bv.x;
                    o.y = cur.y + acc[mt][nt][1] + ms0 * bv.y;
                } else {
                    o.x = acc[mt][nt][0] + bv.x;
                    o.y = acc[mt][nt][1] + bv.y;
                }
                *(float2*)op = o;
            }
            if (r1 < N_NODES) {
                float* op = out + (size_t)r1 * FEATS + C;
                float2 o;
                if (POOL) {
                    float2 cur = *(float2*)op;
                    o.x = cur.x + acc[mt][nt][2] + ms1 * bv.x;
                    o.y = cur.y + acc[mt][nt][3] + ms1 * bv.y;
                } else {
                    o.x = acc[mt][nt][2] + bv.x;
                    o.y = acc[mt][nt][3] + bv.y;
                }
                *(float2*)op = o;
            }
        }
    }
}

__global__ __launch_bounds__(256, 2) void k_gemm_self(
        const float* __restrict__ feat, const float* __restrict__ b_self,
        float* __restrict__ out) {
    gemm_body<0>(feat, b_self, out);
}

__global__ __launch_bounds__(256, 2) void k_gemm_pool(
        const float* __restrict__ b_pool, float* __restrict__ out) {
    gemm_body<1>(g_aggF, b_pool, out);
}

// ---------------- launch: fork k_gemm_self onto a second stream -------------
extern "C" void kernel_launch(void* const* d_in, const int* in_sizes, int n_in,
                              void* d_out, int out_size) {
    const float* feat   = (const float*)d_in[0];
    const float* efeat  = (const float*)d_in[1];
    const int*   src    = (const int*)d_in[2];
    const int*   dst    = (const int*)d_in[3];
    const float* W_pool = (const float*)d_in[4];
    const float* b_pool = (const float*)d_in[5];
    const float* W_self = (const float*)d_in[6];
    const float* b_self = (const float*)d_in[7];
    float* out = (float*)d_out;

    static cudaStream_t s2 = nullptr;
    static cudaEvent_t evFork = nullptr, evJoin = nullptr;
    if (s2 == nullptr) {
        cudaStreamCreateWithFlags(&s2, cudaStreamNonBlocking);
        cudaEventCreateWithFlags(&evFork, cudaEventDisableTiming);
        cudaEventCreateWithFlags(&evJoin, cudaEventDisableTiming);
    }

    k_prep<<<(N_NODES + 255) / 256, 256>>>(W_pool, W_self);

    // fork: self-GEMM depends only on prep; runs concurrent with edge pipeline
    cudaEventRecord(evFork, 0);
    cudaStreamWaitEvent(s2, evFork, 0);
    k_gemm_self<<<(N_NODES + 127) / 128, 256, 0, s2>>>(feat, b_self, out);
    cudaEventRecord(evJoin, s2);

    k_stats<<<(N_EDGES + 255) / 256, 256>>>(efeat, dst);
    k_fill<<<(N_EDGES + 255) / 256, 256>>>(efeat, src, dst);
    k_gather<<<(N_NODES * 32 + 255) / 256, 256>>>(feat);

    // join: pool-GEMM needs both gather (main stream) and self-GEMM (s2)
    cudaStreamWaitEvent(0, evJoin, 0);
    k_gemm_pool<<<(N_NODES + 127) / 128, 256>>>(b_pool, out);
}

// round 17
// speedup vs baseline: 1.3967x; 1.0852x over previous
#include <cuda_runtime.h>
#include <cuda_bf16.h>
#include <cuda_fp16.h>
#include <cstdint>
#include <math.h>

#define N_NODES 50000
#define N_EDGES 800000
#define FEATS   128
#define MAXDEG  128                    // padded-CSR row stride (P(deg>127) ~ 0)

#define WS_SCALE 16777216.0f          // 2^24 fixed-point for wsum
#define PACK_MASK ((1ull << 40) - 1)

#define NQUADS (N_NODES * FEATS / 4)  // 1.6M float4 granules = 2 * N_EDGES

// ---------------- scratch (static __device__, no allocation) ----------------
__device__ unsigned long long g_pack[N_NODES];   // deg<<40 | fixedpoint wsum
__device__ int   g_rank[N_EDGES];                // rank of edge within dst bucket
__device__ unsigned long long g_epack[(size_t)N_NODES * MAXDEG]; // low32=src, high32=m bits
__device__ float g_aggF[(size_t)N_NODES * FEATS];
__device__ float g_ms[N_NODES];
__device__ __align__(16) __half g_featH[(size_t)N_NODES * FEATS];
__device__ __align__(16) unsigned int g_Wh[128 * 128];  // bf16x2 hi, concat-K layout
__device__ __align__(16) unsigned int g_Wl[128 * 128];  // bf16x2 lo

// ---------------- K0: fused init (zero pack) + W split ----------------
__global__ void k_prep(const float* __restrict__ W_pool,
                       const float* __restrict__ W_self) {
    int i = blockIdx.x * blockDim.x + threadIdx.x;
    if (i < N_NODES) g_pack[i] = 0ull;
    if (i < 128 * 128) {
        int j = i >> 7;
        int w = i & 127;
        int k = 2 * w;
        const float* srcp = (k < FEATS) ? (W_self + (size_t)j * FEATS + k)
                                        : (W_pool + (size_t)j * FEATS + (k - FEATS));
        float x = srcp[0], y = srcp[1];
        float hx = __bfloat162float(__float2bfloat16(x));
        float hy = __bfloat162float(__float2bfloat16(y));
        __nv_bfloat16 a, b;
        a = __float2bfloat16(hx); b = __float2bfloat16(hy);
        g_Wh[i] = (uint32_t)__bfloat16_as_ushort(a) | ((uint32_t)__bfloat16_as_ushort(b) << 16);
        a = __float2bfloat16(x - hx); b = __float2bfloat16(y - hy);
        g_Wl[i] = (uint32_t)__bfloat16_as_ushort(a) | ((uint32_t)__bfloat16_as_ushort(b) << 16);
    }
}

// ---------------- K1: deg+wsum atomic + rank capture + feat->fp16 ----------
// The feat conversion (2 quads/thread) is independent streaming work that
// hides under the atomic's latency stalls (stats was issue=6%, L2=31%).
__global__ void k_stats(const float* __restrict__ efeat, const int* __restrict__ dst,
                        const float* __restrict__ feat) {
    int e = blockIdx.x * blockDim.x + threadIdx.x;
    if (e < N_EDGES) {
        int d = dst[e];
        unsigned long long enc = (1ull << 40)
                               | (unsigned long long)__float2uint_rn(efeat[e] * WS_SCALE);
        unsigned long long old = atomicAdd(&g_pack[d], enc);
        g_rank[e] = (int)(old >> 40);
        // feat -> fp16 table: quads e and e + N_EDGES (NQUADS == 2*N_EDGES)
        __half2* o = (__half2*)g_featH;
        float4 v0 = ((const float4*)feat)[e];
        o[e * 2]     = __floats2half2_rn(v0.x, v0.y);
        o[e * 2 + 1] = __floats2half2_rn(v0.z, v0.w);
        int e2 = e + N_EDGES;
        float4 v1 = ((const float4*)feat)[e2];
        o[e2 * 2]     = __floats2half2_rn(v1.x, v1.y);
        o[e2 * 2 + 1] = __floats2half2_rn(v1.z, v1.w);
    }
}

// ---------------- K2: fill padded CSR with precomputed coefficient ----------
__global__ void k_fill(const float* __restrict__ efeat, const int* __restrict__ src,
                       const int* __restrict__ dst) {
    int e = blockIdx.x * blockDim.x + threadIdx.x;
    if (e < N_EDGES) {
        int d = dst[e];
        unsigned long long p = g_pack[d];
        float m = __expf(-__fdividef(efeat[e] * WS_SCALE, (float)(p & PACK_MASK)));
        size_t slot = (size_t)d * MAXDEG + (unsigned int)g_rank[e];
        g_epack[slot] = (unsigned int)src[e]
                      | ((unsigned long long)__float_as_uint(m) << 32);
    }
}

// ---------------- K3: warp-per-node gather over fp16 table ------------------
// (R13-validated loop: 2 edges per uint4 metadata load, coef precomputed.)
__global__ void k_gather() {
    int node = (blockIdx.x * blockDim.x + threadIdx.x) >> 5;
    int lane = threadIdx.x & 31;
    if (node >= N_NODES) return;
    int n = (int)(g_pack[node] >> 40);
    const uint4* row4 = (const uint4*)(g_epack + (size_t)node * MAXDEG);
    const char* fb = (const char*)g_featH + lane * 8;   // 4 halves per lane; row=256B
    float4 acc = make_float4(0.f, 0.f, 0.f, 0.f);
    float msum = 0.f;
    int nPairs = n >> 1;
    #pragma unroll 4
    for (int j = 0; j < nPairs; j++) {
        uint4 v = row4[j];                              // 2 packed edges, broadcast
        float c0 = __uint_as_float(v.y);
        float c1 = __uint_as_float(v.w);
        uint2 h0 = *(const uint2*)(fb + ((size_t)v.x << 8));
        uint2 h1 = *(const uint2*)(fb + ((size_t)v.z << 8));
        float2 a0 = __half22float2(*(__half2*)&h0.x);
        float2 b0 = __half22float2(*(__half2*)&h0.y);
        msum += c0;
        acc.x = fmaf(c0, a0.x, acc.x);
        acc.y = fmaf(c0, a0.y, acc.y);
        acc.z = fmaf(c0, b0.x, acc.z);
        acc.w = fmaf(c0, b0.y, acc.w);
        float2 a1 = __half22float2(*(__half2*)&h1.x);
        float2 b1 = __half22float2(*(__half2*)&h1.y);
        msum += c1;
        acc.x = fmaf(c1, a1.x, acc.x);
        acc.y = fmaf(c1, a1.y, acc.y);
        acc.z = fmaf(c1, b1.x, acc.z);
        acc.w = fmaf(c1, b1.y, acc.w);
    }
    if (n & 1) {
        unsigned long long v = ((const unsigned long long*)row4)[n - 1];
        unsigned int s = (unsigned int)v;
        float c = __uint_as_float((unsigned int)(v >> 32));
        uint2 h = *(const uint2*)(fb + ((size_t)s << 8));
        float2 a = __half22float2(*(__half2*)&h.x);
        float2 b = __half22float2(*(__half2*)&h.y);
        msum += c;
        acc.x = fmaf(c, a.x, acc.x);
        acc.y = fmaf(c, a.y, acc.y);
        acc.z = fmaf(c, b.x, acc.z);
        acc.w = fmaf(c, b.y, acc.w);
    }
    float inv = 1.0f / fmaxf((float)n, 1.0f);
    ((float4*)g_aggF)[(size_t)node * 32 + lane] =
        make_float4(acc.x * inv, acc.y * inv, acc.z * inv, acc.w * inv);
    if (lane == 0) g_ms[node] = msum * inv;
}

// ============================================================================
// K4: split-bf16 GEMM on mma.sync (HMMA). B pre-split (g_Wh/g_Wl).
// (R12-validated version, byte-identical.)
// ============================================================================

#define MMA_BF16(d, A0, A1, A2, A3, B0, B1)                                  \
    asm volatile(                                                            \
        "mma.sync.aligned.m16n8k16.row.col.f32.bf16.bf16.f32 "               \
        "{%0,%1,%2,%3}, {%4,%5,%6,%7}, {%8,%9}, {%0,%1,%2,%3};"              \
        : "+f"(d[0]), "+f"(d[1]), "+f"(d[2]), "+f"(d[3])                     \
        : "r"(A0), "r"(A1), "r"(A2), "r"(A3), "r"(B0), "r"(B1))

__device__ __forceinline__ uint32_t pack_bf16(float a, float b) {
    __nv_bfloat16 x = __float2bfloat16(a);
    __nv_bfloat16 y = __float2bfloat16(b);
    return (uint32_t)__bfloat16_as_ushort(x) | ((uint32_t)__bfloat16_as_ushort(y) << 16);
}

// smem: 4 tiles of 128 rows x (16 data + 2 pad) words = 9216 B each
#define T_AH 0
#define T_AL 9216
#define T_BH 18432
#define T_BL 27648
#define ROWB 72
#define ROWW 18

__global__ __launch_bounds__(256, 2) void k_gemm(
        const float* __restrict__ feat,
        const float* __restrict__ b_pool,
        const float* __restrict__ b_self,
        float* __restrict__ out) {
    __shared__ __align__(16) char sm[36864];

    int tid  = threadIdx.x;
    int wid  = tid >> 5;
    int lane = tid & 31;
    int wr = wid >> 1;
    int wc = wid & 1;
    int lr = lane >> 2;
    int lc = lane & 3;
    int blockRow = blockIdx.x * 128;

    float acc[2][8][4];
    #pragma unroll
    for (int mt = 0; mt < 2; mt++)
        #pragma unroll
        for (int nt = 0; nt < 8; nt++)
            #pragma unroll
            for (int i = 0; i < 4; i++) acc[mt][nt][i] = 0.f;

    for (int c = 0; c < 8; c++) {
        const float* Asrc = (c < 4) ? feat : g_aggF;
        int kOff = (c & 3) * 32;

        __syncthreads();
        // ---- A: 1024 float4 slots, split to bf16 hi/lo ----
        #pragma unroll
        for (int it = 0; it < 4; it++) {
            int idx = tid + it * 256;
            int row = idx >> 3;
            int q   = idx & 7;
            int k0  = q * 4;
            int rg  = blockRow + row;
            int rgc = (rg < N_NODES) ? rg : (N_NODES - 1);
            float4 v = *(const float4*)(Asrc + (size_t)rgc * FEATS + kOff + k0);
            float hx = __bfloat162float(__float2bfloat16(v.x));
            float hy = __bfloat162float(__float2bfloat16(v.y));
            float hz = __bfloat162float(__float2bfloat16(v.z));
            float hw = __bfloat162float(__float2bfloat16(v.w));
            uint2 hp, lp;
            hp.x = pack_bf16(hx, hy);             hp.y = pack_bf16(hz, hw);
            lp.x = pack_bf16(v.x - hx, v.y - hy); lp.y = pack_bf16(v.z - hz, v.w - hw);
            *(uint2*)(sm + T_AH + row * ROWB + q * 8) = hp;
            *(uint2*)(sm + T_AL + row * ROWB + q * 8) = lp;
        }
        // ---- B: copy pre-split weights; 16B gmem loads, 2x 8B smem stores ----
        #pragma unroll
        for (int it = 0; it < 4; it++) {
            int idx = tid + it * 256;
            int row = idx >> 3;
            int t8  = idx & 7;
            int hl  = t8 >> 2;
            int q   = t8 & 3;
            const unsigned int* srcw = (hl ? g_Wl : g_Wh) + row * 128 + c * 16 + q * 4;
            uint4 v = *(const uint4*)srcw;
            char* dstp = sm + (hl ? T_BL : T_BH) + row * ROWB + q * 16;
            *(uint2*)(dstp)     = make_uint2(v.x, v.y);
            *(uint2*)(dstp + 8) = make_uint2(v.z, v.w);
        }
        __syncthreads();

        const uint32_t* pAH = (const uint32_t*)(sm + T_AH);
        const uint32_t* pAL = (const uint32_t*)(sm + T_AL);
        const uint32_t* pBH = (const uint32_t*)(sm + T_BH);
        const uint32_t* pBL = (const uint32_t*)(sm + T_BL);

        #pragma unroll
        for (int ks = 0; ks < 2; ks++) {
            int kb2 = ks * 8;
            uint32_t ah[2][4], al[2][4];
            #pragma unroll
            for (int mt = 0; mt < 2; mt++) {
                int r0 = wr * 32 + mt * 16 + lr;
                int i00 = r0 * ROWW + kb2 + lc;
                ah[mt][0] = pAH[i00];
                ah[mt][1] = pAH[i00 + 8 * ROWW];
                ah[mt][2] = pAH[i00 + 4];
                ah[mt][3] = pAH[i00 + 8 * ROWW + 4];
                al[mt][0] = pAL[i00];
                al[mt][1] = pAL[i00 + 8 * ROWW];
                al[mt][2] = pAL[i00 + 4];
                al[mt][3] = pAL[i00 + 8 * ROWW + 4];
            }
            #pragma unroll
            for (int nt = 0; nt < 8; nt++) {
                int n0 = wc * 64 + nt * 8 + lr;
                int j0 = n0 * ROWW + kb2 + lc;
                uint32_t bh0 = pBH[j0], bh1 = pBH[j0 + 4];
                uint32_t bl0 = pBL[j0], bl1 = pBL[j0 + 4];
                #pragma unroll
                for (int mt = 0; mt < 2; mt++) {
                    MMA_BF16(acc[mt][nt], ah[mt][0], ah[mt][1], ah[mt][2], ah[mt][3], bh0, bh1);
                    MMA_BF16(acc[mt][nt], ah[mt][0], ah[mt][1], ah[mt][2], ah[mt][3], bl0, bl1);
                    MMA_BF16(acc[mt][nt], al[mt][0], al[mt][1], al[mt][2], al[mt][3], bh0, bh1);
                }
            }
        }
    }

    // ---- epilogue: + b_self + ms * b_pool ----
    #pragma unroll
    for (int mt = 0; mt < 2; mt++) {
        int r0 = blockRow + wr * 32 + mt * 16 + lr;
        int r1 = r0 + 8;
        float ms0 = (r0 < N_NODES) ? g_ms[r0] : 0.f;
        float ms1 = (r1 < N_NODES) ? g_ms[r1] : 0.f;
        #pragma unroll
        for (int nt = 0; nt < 8; nt++) {
            int C = wc * 64 + nt * 8 + lc * 2;
            float2 bs = *(const float2*)(b_self + C);
            float2 bp = *(const float2*)(b_pool + C);
            if (r0 < N_NODES) {
                float2 o;
                o.x = acc[mt][nt][0] + bs.x + ms0 * bp.x;
                o.y = acc[mt][nt][1] + bs.y + ms0 * bp.y;
                *(float2*)(out + (size_t)r0 * FEATS + C) = o;
            }
            if (r1 < N_NODES) {
                float2 o;
                o.x = acc[mt][nt][2] + bs.x + ms1 * bp.x;
                o.y = acc[mt][nt][3] + bs.y + ms1 * bp.y;
                *(float2*)(out + (size_t)r1 * FEATS + C) = o;
            }
        }
    }
}

// ---------------- launch ----------------
extern "C" void kernel_launch(void* const* d_in, const int* in_sizes, int n_in,
                              void* d_out, int out_size) {
    const float* feat   = (const float*)d_in[0];
    const float* efeat  = (const float*)d_in[1];
    const int*   src    = (const int*)d_in[2];
    const int*   dst    = (const int*)d_in[3];
    const float* W_pool = (const float*)d_in[4];
    const float* b_pool = (const float*)d_in[5];
    const float* W_self = (const float*)d_in[6];
    const float* b_self = (const float*)d_in[7];
    float* out = (float*)d_out;

    k_prep<<<(N_NODES + 255) / 256, 256>>>(W_pool, W_self);
    k_stats<<<(N_EDGES + 255) / 256, 256>>>(efeat, dst, feat);
    k_fill<<<(N_EDGES + 255) / 256, 256>>>(efeat, src, dst);
    k_gather<<<(N_NODES * 32 + 255) / 256, 256>>>();
    k_gemm<<<(N_NODES + 127) / 128, 256>>>(feat, b_pool, b_self, out);
}